// round 1
// baseline (speedup 1.0000x reference)
#include <cuda_runtime.h>

#define B_   8
#define C_   256
#define CC_  64
#define H_   64
#define W_   64
#define HW_  4096
#define OE_  36       // S^2 * K^2
#define EPSF 1e-5f

// ---------------- scratch (no allocations allowed) ----------------
__device__ float g_comp[B_ * CC_ * HW_];   // 8 MB
__device__ float g_enc [B_ * OE_ * HW_];   // 4.5 MB
__device__ float g_scale[CC_];
__device__ float g_shift[CC_];

// ---------------- K1: 1x1 conv (GEMM 64x256 * 256x(B*HW)) ----------------
// grid 256 blocks: each block = one b, 128 hw positions, all 64 out channels.
// thread tile: 8 o x 4 hw.
__global__ __launch_bounds__(256) void k1_compress(
    const float* __restrict__ x, const float* __restrict__ w1,
    const float* __restrict__ b1)
{
    __shared__ float sx[16][128];
    __shared__ float sw[16][64];
    int t   = blockIdx.x;
    int b   = t >> 5;              // 32 tiles per batch
    int hw0 = (t & 31) * 128;
    int tid = threadIdx.x;
    int og  = tid >> 5;            // 0..7  -> o = og*8 + oo
    int hg  = tid & 31;            // 0..31 -> hw = hw0 + hg*4 + p

    float acc[8][4];
#pragma unroll
    for (int i = 0; i < 8; i++)
#pragma unroll
        for (int p = 0; p < 4; p++) acc[i][p] = 0.f;

    const float* xb = x + (size_t)b * C_ * HW_ + hw0;
    for (int cb = 0; cb < C_; cb += 16) {
#pragma unroll
        for (int k = 0; k < 8; k++) {
            int idx = tid + k * 256;
            int kc = idx >> 7, hl = idx & 127;
            sx[kc][hl] = xb[(cb + kc) * HW_ + hl];
        }
#pragma unroll
        for (int k = 0; k < 4; k++) {
            int idx = tid + k * 256;
            int kc = idx >> 6, o = idx & 63;
            sw[kc][o] = w1[o * C_ + cb + kc];
        }
        __syncthreads();
#pragma unroll
        for (int kc = 0; kc < 16; kc++) {
            float4 xv  = *(const float4*)&sx[kc][hg * 4];
            float4 wa  = *(const float4*)&sw[kc][og * 8];
            float4 wb  = *(const float4*)&sw[kc][og * 8 + 4];
            float wv[8] = {wa.x, wa.y, wa.z, wa.w, wb.x, wb.y, wb.z, wb.w};
#pragma unroll
            for (int oo = 0; oo < 8; oo++) {
                acc[oo][0] += wv[oo] * xv.x;
                acc[oo][1] += wv[oo] * xv.y;
                acc[oo][2] += wv[oo] * xv.z;
                acc[oo][3] += wv[oo] * xv.w;
            }
        }
        __syncthreads();
    }
#pragma unroll
    for (int oo = 0; oo < 8; oo++) {
        int o = og * 8 + oo;
        float bias = b1[o];
        float4 r = {acc[oo][0] + bias, acc[oo][1] + bias,
                    acc[oo][2] + bias, acc[oo][3] + bias};
        *(float4*)&g_comp[((size_t)b * CC_ + o) * HW_ + hw0 + hg * 4] = r;
    }
}

// ---------------- K2: per-channel batch stats -> BN scale/shift ----------------
__global__ __launch_bounds__(256) void k2_stats(
    const float* __restrict__ gamma, const float* __restrict__ beta)
{
    __shared__ float ss[256], sq[256];
    int o = blockIdx.x, tid = threadIdx.x;
    float s = 0.f, q = 0.f;
    for (int t = tid; t < B_ * HW_; t += 256) {
        int b = t >> 12, i = t & 4095;
        float v = g_comp[((size_t)b * CC_ + o) * HW_ + i];
        s += v; q += v * v;
    }
    ss[tid] = s; sq[tid] = q;
    __syncthreads();
    for (int st = 128; st > 0; st >>= 1) {
        if (tid < st) { ss[tid] += ss[tid + st]; sq[tid] += sq[tid + st]; }
        __syncthreads();
    }
    if (tid == 0) {
        float n = (float)(B_ * HW_);
        float mean = ss[0] / n;
        float var  = sq[0] / n - mean * mean;      // biased, like torch BN
        float sc   = gamma[o] * rsqrtf(var + EPSF);
        g_scale[o] = sc;
        g_shift[o] = beta[o] - mean * sc;
    }
}

// ---------------- K3: 3x3 conv 64->36 (BN+ReLU fused at smem load) ----------------
// grid (4,4,8): 16x16 spatial tile per block. threads: 4 o-groups(x9) x 64 pix-groups(x4, 2x2).
__global__ __launch_bounds__(256) void k3_conv(
    const float* __restrict__ w2, const float* __restrict__ b2)
{
    __shared__ float xs[8][18][19];
    __shared__ float ws[8][9][36];
    __shared__ float ssc[64], ssh[64];
    int w0 = blockIdx.x * 16, h0 = blockIdx.y * 16, b = blockIdx.z;
    int tid = threadIdx.x;
    if (tid < 64) { ssc[tid] = g_scale[tid]; ssh[tid] = g_shift[tid]; }
    int og  = tid >> 6;              // 0..3, o0 = og*9
    int pg  = tid & 63;
    int py0 = (pg >> 3) * 2, px0 = (pg & 7) * 2;

    float acc[9][4];
#pragma unroll
    for (int i = 0; i < 9; i++)
#pragma unroll
        for (int p = 0; p < 4; p++) acc[i][p] = 0.f;

    const float* compb = g_comp + (size_t)b * CC_ * HW_;
    for (int cb = 0; cb < 64; cb += 8) {
        __syncthreads();
        for (int idx = tid; idx < 2592; idx += 256) {       // 8*18*18
            int ci = idx / 324; int rem = idx - ci * 324;
            int r = rem / 18;   int cc  = rem - r * 18;
            int gy = h0 + r - 1, gx = w0 + cc - 1;
            float v = 0.f;
            if (gy >= 0 && gy < 64 && gx >= 0 && gx < 64) {
                float raw = compb[(cb + ci) * HW_ + gy * 64 + gx];
                v = fmaxf(raw * ssc[cb + ci] + ssh[cb + ci], 0.f);
            }
            xs[ci][r][cc] = v;
        }
        for (int idx = tid; idx < 2592; idx += 256) {       // 8*9*36
            int ci = idx / 324; int rem = idx - ci * 324;
            int ij = rem / 36;  int o   = rem - ij * 36;
            ws[ci][ij][o] = w2[(o * 64 + cb + ci) * 9 + ij];
        }
        __syncthreads();
#pragma unroll
        for (int ci = 0; ci < 8; ci++) {
#pragma unroll
            for (int ij = 0; ij < 9; ij++) {
                int i = ij / 3, j = ij % 3;
                float v0 = xs[ci][py0 + i][px0 + j];
                float v1 = xs[ci][py0 + i][px0 + j + 1];
                float v2 = xs[ci][py0 + i + 1][px0 + j];
                float v3 = xs[ci][py0 + i + 1][px0 + j + 1];
#pragma unroll
                for (int oo = 0; oo < 9; oo++) {
                    float wv = ws[ci][ij][og * 9 + oo];
                    acc[oo][0] += wv * v0;
                    acc[oo][1] += wv * v1;
                    acc[oo][2] += wv * v2;
                    acc[oo][3] += wv * v3;
                }
            }
        }
    }
#pragma unroll
    for (int oo = 0; oo < 9; oo++) {
        int o = og * 9 + oo;
        float bias = b2[o];
        float* e = g_enc + ((size_t)b * OE_ + o) * HW_;
        float2 r0 = {acc[oo][0] + bias, acc[oo][1] + bias};
        float2 r1 = {acc[oo][2] + bias, acc[oo][3] + bias};
        *(float2*)&e[(h0 + py0    ) * 64 + w0 + px0] = r0;
        *(float2*)&e[(h0 + py0 + 1) * 64 + w0 + px0] = r1;
    }
}

// ---------------- K4: softmax over H (faithful-to-source axis=1) ----------------
// one thread per (b, channel, w) column of 64 H values; in-place on g_enc.
__global__ __launch_bounds__(256) void k4_softmax()
{
    int idx = blockIdx.x * 256 + threadIdx.x;    // 8*36*64 = 18432 exactly
    int w  = idx & 63;
    int ch = (idx >> 6) % 36;
    int b  = idx / (64 * 36);
    float* base = g_enc + (((size_t)b * 36 + ch) * 64) * 64 + w;
    float v[64];
    float m = -1e30f;
#pragma unroll
    for (int h = 0; h < 64; h++) { v[h] = base[h * 64]; m = fmaxf(m, v[h]); }
    float s = 0.f;
#pragma unroll
    for (int h = 0; h < 64; h++) { v[h] = __expf(v[h] - m); s += v[h]; }
    float inv = 1.f / s;
#pragma unroll
    for (int h = 0; h < 64; h++) base[h * 64] = v[h] * inv;
}

// ---------------- K5: CARAFE reassembly + scrambled output layout ----------------
// grid (64, 8) = (h, b). block: 256 threads = 4 c-groups x 64 w.
// out[b, s*64+(c>>2), 2h+((c&3)>>1), ((c&3)&1)*64+w] = sum_k2 x_unf * kern
__global__ __launch_bounds__(256) void k5_carafe(
    const float* __restrict__ x, float* __restrict__ out)
{
    __shared__ float ks[64][37];        // softmaxed kernels for this (b,h) row
    __shared__ float xs[3][32][64];     // 3 input rows x 32-channel chunk x W
    int h = blockIdx.x, b = blockIdx.y;
    int tid = threadIdx.x;
    int wt = tid & 63, cg = tid >> 6;

    for (int idx = tid; idx < 36 * 64; idx += 256) {
        int ch = idx >> 6, w = idx & 63;
        ks[w][ch] = g_enc[(((size_t)b * 36 + ch) * 64 + h) * 64 + w];
    }
    __syncthreads();

    float kr[4][9];
#pragma unroll
    for (int s = 0; s < 4; s++)
#pragma unroll
        for (int k2 = 0; k2 < 9; k2++) kr[s][k2] = ks[wt][s * 9 + k2];

    int wl = wt > 0 ? wt - 1 : 0;
    int wr = wt < 63 ? wt + 1 : 63;
    int hr0 = h > 0 ? h - 1 : 0;
    int hr2 = h < 63 ? h + 1 : 63;
    int hrow[3] = {hr0, h, hr2};
    float* outb = out + (size_t)b * C_ * 128 * 128;

    for (int cb = 0; cb < 256; cb += 32) {
        __syncthreads();
#pragma unroll
        for (int k = 0; k < 6; k++) {                 // 1536 float4 loads
            int q  = tid + k * 256;
            int dr = q / 512;
            int cl = (q >> 4) & 31;
            int wq = q & 15;
            ((float4*)xs)[q] =
                ((const float4*)(x + (((size_t)b * C_ + cb + cl) * 64 + hrow[dr]) * 64))[wq];
        }
        __syncthreads();
#pragma unroll
        for (int cc = 0; cc < 8; cc++) {
            int cl = cg * 8 + cc;
            const float* r0 = &xs[0][cl][0];
            const float* r1 = &xs[1][cl][0];
            const float* r2 = &xs[2][cl][0];
            float vals[9];
            vals[0] = r0[wl]; vals[1] = r0[wt]; vals[2] = r0[wr];
            vals[3] = r1[wl]; vals[4] = r1[wt]; vals[5] = r1[wr];
            vals[6] = r2[wl]; vals[7] = r2[wt]; vals[8] = r2[wr];
            float a0 = 0.f, a1 = 0.f, a2 = 0.f, a3 = 0.f;
#pragma unroll
            for (int k2 = 0; k2 < 9; k2++) {
                a0 += vals[k2] * kr[0][k2];
                a1 += vals[k2] * kr[1][k2];
                a2 += vals[k2] * kr[2][k2];
                a3 += vals[k2] * kr[3][k2];
            }
            int c   = cb + cl;
            int s4  = c & 3;
            int row = 2 * h + (s4 >> 1);
            int col = ((s4 & 1) << 6) + wt;
            int c4b = c >> 2;
            outb[((0 * 64 + c4b) * 128 + row) * 128 + col] = a0;
            outb[((1 * 64 + c4b) * 128 + row) * 128 + col] = a1;
            outb[((2 * 64 + c4b) * 128 + row) * 128 + col] = a2;
            outb[((3 * 64 + c4b) * 128 + row) * 128 + col] = a3;
        }
    }
}

// ---------------- launch ----------------
extern "C" void kernel_launch(void* const* d_in, const int* in_sizes, int n_in,
                              void* d_out, int out_size)
{
    const float* x     = (const float*)d_in[0];
    const float* w1    = (const float*)d_in[1];
    const float* b1    = (const float*)d_in[2];
    const float* gamma = (const float*)d_in[3];
    const float* beta  = (const float*)d_in[4];
    const float* w2    = (const float*)d_in[5];
    const float* b2    = (const float*)d_in[6];
    float* out = (float*)d_out;

    k1_compress<<<256, 256>>>(x, w1, b1);
    k2_stats<<<64, 256>>>(gamma, beta);
    k3_conv<<<dim3(4, 4, 8), 256>>>(w2, b2);
    k4_softmax<<<72, 256>>>();
    k5_carafe<<<dim3(64, 8), 256>>>(x, out);
}

// round 3
// speedup vs baseline: 1.0430x; 1.0430x over previous
#include <cuda_runtime.h>

#define B_   8
#define C_   256
#define CC_  64
#define H_   64
#define W_   64
#define HW_  4096
#define OE_  36
#define EPSF 1e-5f

typedef unsigned long long u64;

__device__ __forceinline__ u64 pk2(float lo, float hi) {
    u64 r; asm("mov.b64 %0, {%1,%2};" : "=l"(r) : "f"(lo), "f"(hi)); return r;
}
__device__ __forceinline__ u64 splat2(float v) { return pk2(v, v); }
__device__ __forceinline__ void fma2(u64& d, u64 a, u64 b) {
    asm("fma.rn.f32x2 %0, %1, %2, %0;" : "+l"(d) : "l"(a), "l"(b));
}
__device__ __forceinline__ float2 up2(u64 v) {
    float2 f; asm("mov.b64 {%0,%1}, %2;" : "=f"(f.x), "=f"(f.y) : "l"(v)); return f;
}

// ---------------- scratch ----------------
__device__ float g_comp[B_ * CC_ * HW_];
__device__ float g_enc [B_ * OE_ * HW_];
__device__ float g_scale[CC_];
__device__ float g_shift[CC_];
__device__ float g_wt[CC_ * 9 * OE_];      // w2 transposed: [(c*9+ij)*36 + o]

// ---------------- K0: transpose w2 once for coalesced smem fills ----------------
__global__ __launch_bounds__(256) void k0_wt(const float* __restrict__ w2)
{
    int idx = blockIdx.x * 256 + threadIdx.x;
    if (idx >= CC_ * 9 * OE_) return;
    int o = idx % 36;
    int t = idx / 36;
    int ij = t % 9, c = t / 9;
    g_wt[idx] = w2[(o * CC_ + c) * 9 + ij];
}

// ---------------- K1: 1x1 conv GEMM, f32x2 packed ----------------
__global__ __launch_bounds__(256) void k1_compress(
    const float* __restrict__ x, const float* __restrict__ w1,
    const float* __restrict__ b1)
{
    __shared__ __align__(16) float sx[16][128];
    __shared__ u64 swd[16][64];
    int b   = blockIdx.x >> 5;
    int hw0 = (blockIdx.x & 31) * 128;
    int tid = threadIdx.x;
    int og  = tid >> 5;            // warp-uniform
    int hg  = tid & 31;

    u64 acc[8][2];
#pragma unroll
    for (int i = 0; i < 8; i++) { acc[i][0] = 0ull; acc[i][1] = 0ull; }

    const float* xb = x + (size_t)b * C_ * HW_ + hw0;
    for (int cb = 0; cb < C_; cb += 16) {
#pragma unroll
        for (int k = 0; k < 2; k++) {              // 512 float4
            int q = tid + k * 256;
            int kc = q >> 5, hl = q & 31;
            ((float4*)sx[kc])[hl] = ((const float4*)(xb + (size_t)(cb + kc) * HW_))[hl];
        }
#pragma unroll
        for (int k = 0; k < 4; k++) {              // 1024 pre-splatted weights
            int q = tid + k * 256;
            int kc = q >> 6, o = q & 63;
            swd[kc][o] = splat2(w1[o * C_ + cb + kc]);
        }
        __syncthreads();
#pragma unroll
        for (int kc = 0; kc < 16; kc++) {
            ulonglong2 xv = *(const ulonglong2*)&sx[kc][hg * 4];
#pragma unroll
            for (int oo = 0; oo < 8; oo++) {
                u64 wd = swd[kc][og * 8 + oo];     // broadcast LDS.64
                fma2(acc[oo][0], wd, xv.x);
                fma2(acc[oo][1], wd, xv.y);
            }
        }
        __syncthreads();
    }
#pragma unroll
    for (int oo = 0; oo < 8; oo++) {
        int o = og * 8 + oo;
        float bias = b1[o];
        float2 lo = up2(acc[oo][0]), hi = up2(acc[oo][1]);
        float4 r = {lo.x + bias, lo.y + bias, hi.x + bias, hi.y + bias};
        *(float4*)&g_comp[((size_t)b * CC_ + o) * HW_ + hw0 + hg * 4] = r;
    }
}

// ---------------- K2: batch stats -> BN scale/shift ----------------
__global__ __launch_bounds__(256) void k2_stats(
    const float* __restrict__ gamma, const float* __restrict__ beta)
{
    __shared__ float ss[256], sq[256];
    int o = blockIdx.x, tid = threadIdx.x;
    float s = 0.f, q = 0.f;
    for (int t = tid; t < B_ * HW_ / 4; t += 256) {
        int b = t >> 10, i4 = t & 1023;
        float4 v = ((const float4*)&g_comp[((size_t)b * CC_ + o) * HW_])[i4];
        s += v.x + v.y + v.z + v.w;
        q += v.x * v.x + v.y * v.y + v.z * v.z + v.w * v.w;
    }
    ss[tid] = s; sq[tid] = q;
    __syncthreads();
    for (int st = 128; st > 0; st >>= 1) {
        if (tid < st) { ss[tid] += ss[tid + st]; sq[tid] += sq[tid + st]; }
        __syncthreads();
    }
    if (tid == 0) {
        float n = (float)(B_ * HW_);
        float mean = ss[0] / n;
        float var  = sq[0] / n - mean * mean;
        float sc   = gamma[o] * rsqrtf(var + EPSF);
        g_scale[o] = sc;
        g_shift[o] = beta[o] - mean * sc;
    }
}

// ---------------- K3: 3x3 conv 64->36, f32x2 over o-pairs ----------------
// grid (4,8,8): 16x8 tile. 384 threads = 6 o-groups(x6 outs) x 64 px-groups(2x1).
__global__ __launch_bounds__(384) void k3_conv(const float* __restrict__ b2)
{
    __shared__ __align__(16) float xs[8][10][20];
    __shared__ __align__(16) float ws[8][9][36];
    __shared__ float ssc[64], ssh[64];
    int w0 = blockIdx.x * 16, h0 = blockIdx.y * 8, b = blockIdx.z;
    int tid = threadIdx.x;
    if (tid < 64) { ssc[tid] = g_scale[tid]; ssh[tid] = g_shift[tid]; }
    int og  = tid / 64;            // 0..5 (warp-uniform: 64 = 2 warps per og)
    int pg  = tid & 63;
    int px0 = (pg & 7) * 2;
    int py  = pg >> 3;

    u64 acc[3][2];
#pragma unroll
    for (int i = 0; i < 3; i++) { acc[i][0] = 0ull; acc[i][1] = 0ull; }

    const float* compb = g_comp + (size_t)b * CC_ * HW_;
    for (int cb = 0; cb < 64; cb += 8) {
        __syncthreads();
        for (int idx = tid; idx < 1440; idx += 384) {     // 8*10*18
            int ci = idx / 180; int rem = idx - ci * 180;
            int r = rem / 18;   int cc = rem - r * 18;
            int gy = h0 + r - 1, gx = w0 + cc - 1;
            float v = 0.f;
            if (gy >= 0 && gy < 64 && gx >= 0 && gx < 64) {
                float raw = compb[(cb + ci) * HW_ + gy * 64 + gx];
                v = fmaxf(raw * ssc[cb + ci] + ssh[cb + ci], 0.f);
            }
            xs[ci][r][cc] = v;
        }
        for (int idx = tid; idx < 2592; idx += 384) {     // coalesced from g_wt
            int ci = idx / 324; int rem = idx - ci * 324;
            int ij = rem / 36;  int o = rem - ij * 36;
            ws[ci][ij][o] = g_wt[((cb + ci) * 9 + ij) * 36 + o];
        }
        __syncthreads();
#pragma unroll 2
        for (int ci = 0; ci < 8; ci++) {
            u64 vs[3][4];
#pragma unroll
            for (int r = 0; r < 3; r++) {
                float2 a = *(const float2*)&xs[ci][py + r][px0];
                float2 c = *(const float2*)&xs[ci][py + r][px0 + 2];
                vs[r][0] = splat2(a.x); vs[r][1] = splat2(a.y);
                vs[r][2] = splat2(c.x); vs[r][3] = splat2(c.y);
            }
#pragma unroll
            for (int ij = 0; ij < 9; ij++) {
                int i = ij / 3, j = ij % 3;
#pragma unroll
                for (int op = 0; op < 3; op++) {
                    u64 wd = *(const u64*)&ws[ci][ij][og * 6 + 2 * op];
                    fma2(acc[op][0], vs[i][j],     wd);
                    fma2(acc[op][1], vs[i][j + 1], wd);
                }
            }
        }
    }
#pragma unroll
    for (int op = 0; op < 3; op++) {
        int o = og * 6 + 2 * op;
        float2 r0 = up2(acc[op][0]);   // (o, o+1) at px0
        float2 r1 = up2(acc[op][1]);   // (o, o+1) at px0+1
        float bia0 = b2[o], bia1 = b2[o + 1];
        float* e0 = g_enc + ((size_t)b * OE_ + o) * HW_ + (h0 + py) * 64 + w0 + px0;
        float* e1 = e0 + HW_;
        *(float2*)e0 = make_float2(r0.x + bia0, r1.x + bia0);
        *(float2*)e1 = make_float2(r0.y + bia1, r1.y + bia1);
    }
}

// ---------------- K4: softmax over H, block per (b,ch) ----------------
__global__ __launch_bounds__(256) void k4_softmax()
{
    __shared__ float red[4][64];
    int b = blockIdx.x / 36, ch = blockIdx.x % 36;
    int tid = threadIdx.x;
    int w = tid & 63, hq = tid >> 6;
    float* base = g_enc + ((size_t)b * 36 + ch) * HW_;
    float v[16];
    float m = -1e30f;
#pragma unroll
    for (int i = 0; i < 16; i++) {
        v[i] = base[(hq * 16 + i) * 64 + w];
        m = fmaxf(m, v[i]);
    }
    red[hq][w] = m;
    __syncthreads();
    m = fmaxf(fmaxf(red[0][w], red[1][w]), fmaxf(red[2][w], red[3][w]));
    float s = 0.f;
#pragma unroll
    for (int i = 0; i < 16; i++) { v[i] = __expf(v[i] - m); s += v[i]; }
    __syncthreads();
    red[hq][w] = s;
    __syncthreads();
    float inv = 1.f / (red[0][w] + red[1][w] + red[2][w] + red[3][w]);
#pragma unroll
    for (int i = 0; i < 16; i++) base[(hq * 16 + i) * 64 + w] = v[i] * inv;
}

// ---------------- K5: CARAFE reassembly, f32x2 over w-pairs, STG.64 ----------------
// grid (64, 8). 256 threads = 8 c-groups(x4 c) x 32 w-pairs.
__global__ __launch_bounds__(256) void k5_carafe(
    const float* __restrict__ x, float* __restrict__ out)
{
    __shared__ __align__(16) float xs[3][32][64];
    int h = blockIdx.x, b = blockIdx.y;
    int tid = threadIdx.x;
    int wt2 = tid & 31, cg = tid >> 5;
    int w0 = 2 * wt2;

    // softmaxed kernel pairs for (w0, w0+1): 36 x LDG.64 (coalesced, L2-shared)
    u64 kr2[4][9];
    const float* encb = g_enc + (size_t)b * 36 * HW_ + h * 64 + w0;
#pragma unroll
    for (int s = 0; s < 4; s++)
#pragma unroll
        for (int k = 0; k < 9; k++)
            kr2[s][k] = *(const u64*)(encb + (size_t)(s * 9 + k) * HW_);

    int hr0 = h > 0 ? h - 1 : 0;
    int hr2 = h < 63 ? h + 1 : 63;
    int hrow[3] = {hr0, h, hr2};
    int cm1 = w0 > 0 ? w0 - 1 : 0;
    int cp2 = w0 + 2 < 64 ? w0 + 2 : 63;
    float* outb = out + (size_t)b * C_ * 128 * 128;

    for (int cb = 0; cb < 256; cb += 32) {
        __syncthreads();
#pragma unroll
        for (int k = 0; k < 6; k++) {
            int q = tid + k * 256;
            int dr = q / 512;
            int cl = (q >> 4) & 31;
            int wq = q & 15;
            ((float4*)xs)[q] =
                ((const float4*)(x + (((size_t)b * C_ + cb + cl) * 64 + hrow[dr]) * 64))[wq];
        }
        __syncthreads();
#pragma unroll
        for (int cc = 0; cc < 4; cc++) {
            int cl = cg * 4 + cc;
            u64 p[3][3];
#pragma unroll
            for (int r = 0; r < 3; r++) {
                const float* row = &xs[r][cl][0];
                float  a = row[cm1];
                u64    mid = *(const u64*)&row[w0];   // (w0, w0+1)
                float  d = row[cp2];
                float2 mf = up2(mid);
                p[r][0] = pk2(a, mf.x);
                p[r][1] = mid;
                p[r][2] = pk2(mf.y, d);
            }
            u64 acc[4] = {0ull, 0ull, 0ull, 0ull};
#pragma unroll
            for (int k2 = 0; k2 < 9; k2++) {
                int i = k2 / 3, j = k2 % 3;
                fma2(acc[0], p[i][j], kr2[0][k2]);
                fma2(acc[1], p[i][j], kr2[1][k2]);
                fma2(acc[2], p[i][j], kr2[2][k2]);
                fma2(acc[3], p[i][j], kr2[3][k2]);
            }
            int c = cb + cl;
            int s4 = c & 3;
            int row_o = 2 * h + (s4 >> 1);
            int colb = ((s4 & 1) << 6) + w0;
            int c4b = c >> 2;
#pragma unroll
            for (int s = 0; s < 4; s++)
                *(u64*)&outb[(((size_t)(s * 64 + c4b)) * 128 + row_o) * 128 + colb] = acc[s];
        }
    }
}

// ---------------- launch ----------------
extern "C" void kernel_launch(void* const* d_in, const int* in_sizes, int n_in,
                              void* d_out, int out_size)
{
    const float* x     = (const float*)d_in[0];
    const float* w1    = (const float*)d_in[1];
    const float* b1    = (const float*)d_in[2];
    const float* gamma = (const float*)d_in[3];
    const float* beta  = (const float*)d_in[4];
    const float* w2    = (const float*)d_in[5];
    const float* b2    = (const float*)d_in[6];
    float* out = (float*)d_out;

    k0_wt<<<81, 256>>>(w2);
    k1_compress<<<256, 256>>>(x, w1, b1);
    k2_stats<<<64, 256>>>(gamma, beta);
    k3_conv<<<dim3(4, 8, 8), 384>>>(b2);
    k4_softmax<<<288, 256>>>();
    k5_carafe<<<dim3(64, 8), 256>>>(x, out);
}

// round 5
// speedup vs baseline: 1.0969x; 1.0518x over previous
#include <cuda_runtime.h>

#define B_   8
#define C_   256
#define CC_  64
#define H_   64
#define W_   64
#define HW_  4096
#define OE_  36
#define EPSF 1e-5f

typedef unsigned long long u64;

__device__ __forceinline__ u64 pk2(float lo, float hi) {
    u64 r; asm("mov.b64 %0, {%1,%2};" : "=l"(r) : "f"(lo), "f"(hi)); return r;
}
__device__ __forceinline__ u64 splat2(float v) { return pk2(v, v); }
__device__ __forceinline__ void fma2(u64& d, u64 a, u64 b) {
    asm("fma.rn.f32x2 %0, %1, %2, %0;" : "+l"(d) : "l"(a), "l"(b));
}
__device__ __forceinline__ float2 up2(u64 v) {
    float2 f; asm("mov.b64 {%0,%1}, %2;" : "=f"(f.x), "=f"(f.y) : "l"(v)); return f;
}

// ---------------- scratch ----------------
__device__ float g_comp[B_ * CC_ * HW_];
__device__ float g_enc [B_ * OE_ * HW_];
__device__ float g_scale[CC_];
__device__ float g_shift[CC_];
// w2 transposed + padded: [(c*9+ij)*48 + (o/6)*8 + o%6]
__device__ float g_wt[CC_ * 9 * 48];

// ---------------- K0: transpose+pad w2 once ----------------
__global__ __launch_bounds__(256) void k0_wt(const float* __restrict__ w2)
{
    int idx = blockIdx.x * 256 + threadIdx.x;
    if (idx >= CC_ * 9 * OE_) return;
    int o = idx % 36;
    int t = idx / 36;
    int ij = t % 9, c = t / 9;
    g_wt[t * 48 + (o / 6) * 8 + (o % 6)] = w2[(o * CC_ + c) * 9 + ij];
}

// ---------------- K1: 1x1 conv GEMM, f32x2 packed over pixel pairs ----------------
__global__ __launch_bounds__(256) void k1_compress(
    const float* __restrict__ x, const float* __restrict__ w1,
    const float* __restrict__ b1)
{
    __shared__ __align__(16) float sx[16][128];
    __shared__ __align__(16) u64 swd[16][64];
    int b   = blockIdx.x >> 5;
    int hw0 = (blockIdx.x & 31) * 128;
    int tid = threadIdx.x;
    int og  = tid >> 5;            // warp-uniform
    int hg  = tid & 31;

    u64 acc[8][2];
#pragma unroll
    for (int i = 0; i < 8; i++) { acc[i][0] = 0ull; acc[i][1] = 0ull; }

    const float* xb = x + (size_t)b * C_ * HW_ + hw0;
    for (int cb = 0; cb < C_; cb += 16) {
#pragma unroll
        for (int k = 0; k < 2; k++) {
            int q = tid + k * 256;
            int kc = q >> 5, hl = q & 31;
            ((float4*)sx[kc])[hl] = ((const float4*)(xb + (size_t)(cb + kc) * HW_))[hl];
        }
#pragma unroll
        for (int k = 0; k < 4; k++) {
            int q = tid + k * 256;
            int kc = q >> 6, o = q & 63;
            swd[kc][o] = splat2(w1[o * C_ + cb + kc]);
        }
        __syncthreads();
#pragma unroll
        for (int kc = 0; kc < 16; kc++) {
            ulonglong2 xv = *(const ulonglong2*)&sx[kc][hg * 4];
#pragma unroll
            for (int k = 0; k < 4; k++) {          // LDS.128 broadcast: 2 weight splats
                ulonglong2 wp = *(const ulonglong2*)&swd[kc][og * 8 + 2 * k];
                fma2(acc[2 * k][0],     wp.x, xv.x);
                fma2(acc[2 * k][1],     wp.x, xv.y);
                fma2(acc[2 * k + 1][0], wp.y, xv.x);
                fma2(acc[2 * k + 1][1], wp.y, xv.y);
            }
        }
        __syncthreads();
    }
#pragma unroll
    for (int oo = 0; oo < 8; oo++) {
        int o = og * 8 + oo;
        float bias = b1[o];
        float2 lo = up2(acc[oo][0]), hi = up2(acc[oo][1]);
        float4 r = {lo.x + bias, lo.y + bias, hi.x + bias, hi.y + bias};
        *(float4*)&g_comp[((size_t)b * CC_ + o) * HW_ + hw0 + hg * 4] = r;
    }
}

// ---------------- K2: batch stats -> BN scale/shift ----------------
__global__ __launch_bounds__(256) void k2_stats(
    const float* __restrict__ gamma, const float* __restrict__ beta)
{
    __shared__ float ss[256], sq[256];
    int o = blockIdx.x, tid = threadIdx.x;
    float s = 0.f, q = 0.f;
    for (int t = tid; t < B_ * HW_ / 4; t += 256) {
        int b = t >> 10, i4 = t & 1023;
        float4 v = ((const float4*)&g_comp[((size_t)b * CC_ + o) * HW_])[i4];
        s += v.x + v.y + v.z + v.w;
        q += v.x * v.x + v.y * v.y + v.z * v.z + v.w * v.w;
    }
    ss[tid] = s; sq[tid] = q;
    __syncthreads();
    for (int st = 128; st > 0; st >>= 1) {
        if (tid < st) { ss[tid] += ss[tid + st]; sq[tid] += sq[tid + st]; }
        __syncthreads();
    }
    if (tid == 0) {
        float n = (float)(B_ * HW_);
        float mean = ss[0] / n;
        float var  = sq[0] / n - mean * mean;
        float sc   = gamma[o] * rsqrtf(var + EPSF);
        g_scale[o] = sc;
        g_shift[o] = beta[o] - mean * sc;
    }
}

// ---------------- K3: 3x3 conv 64->36, f32x2 o-pairs, 4px/thread ----------------
// grid (4,8,8): tile 16w x 8h. 192 threads = 6 warps, warp og = 6 outs.
// lane: py = lane>>2 (row 0..7), px0 = (lane&3)*4 (4 contiguous pixels).
// xs transposed [ci][col][row] -> conflict-free scalar LDS (addr = 8q+py mod 32).
__global__ __launch_bounds__(192) void k3_conv(const float* __restrict__ b2)
{
    __shared__ __align__(16) float xs[8][18][10];  // [ci][col][row]
    __shared__ __align__(16) float ws[8 * 9 * 48]; // flat padded copy of g_wt chunk
    __shared__ float ssc[64], ssh[64];
    int w0 = blockIdx.x * 16, h0 = blockIdx.y * 8, b = blockIdx.z;
    int tid = threadIdx.x;
    if (tid < 64) { ssc[tid] = g_scale[tid]; ssh[tid] = g_shift[tid]; }
    int og   = tid >> 5;           // 0..5, warp-uniform
    int lane = tid & 31;
    int py   = lane >> 2;          // 0..7
    int px0  = (lane & 3) * 4;     // 0,4,8,12

    u64 acc[3][4];
#pragma unroll
    for (int op = 0; op < 3; op++)
#pragma unroll
        for (int p = 0; p < 4; p++) acc[op][p] = 0ull;

    const float* compb = g_comp + (size_t)b * CC_ * HW_;
    for (int cb = 0; cb < 64; cb += 8) {
        __syncthreads();
        for (int idx = tid; idx < 1440; idx += 192) {       // 8ci * 10row * 18col
            int ci = idx / 180; int rem = idx - ci * 180;
            int row = rem / 18; int col = rem - row * 18;
            int gy = h0 + row - 1, gx = w0 + col - 1;
            float v = 0.f;
            if (gy >= 0 && gy < 64 && gx >= 0 && gx < 64) {
                float raw = compb[(cb + ci) * HW_ + gy * 64 + gx];
                v = fmaxf(raw * ssc[cb + ci] + ssh[cb + ci], 0.f);
            }
            xs[ci][col][row] = v;
        }
        {   // flat float4 copy of padded weights: 8*9*48 = 3456 words = 864 float4
            const float4* src = (const float4*)(g_wt + cb * 9 * 48);
            for (int idx = tid; idx < 864; idx += 192)
                ((float4*)ws)[idx] = src[idx];
        }
        __syncthreads();
#pragma unroll
        for (int ci = 0; ci < 8; ci++) {
            u64 s[3][6];
#pragma unroll
            for (int k = 0; k < 6; k++)
#pragma unroll
                for (int r = 0; r < 3; r++)
                    s[r][k] = splat2(xs[ci][px0 + k][py + r]);
            const float* wci = ws + ci * 432 + og * 8;
#pragma unroll
            for (int ij = 0; ij < 9; ij++) {
                int i = ij / 3, j = ij % 3;
                ulonglong2 wab = *(const ulonglong2*)(wci + ij * 48);      // (o0,o1),(o2,o3)
                u64 wc = *(const u64*)(wci + ij * 48 + 4);                 // (o4,o5)
#pragma unroll
                for (int p = 0; p < 4; p++) {
                    fma2(acc[0][p], s[i][j + p], wab.x);
                    fma2(acc[1][p], s[i][j + p], wab.y);
                    fma2(acc[2][p], s[i][j + p], wc);
                }
            }
        }
    }
#pragma unroll
    for (int op = 0; op < 3; op++) {
        int o = og * 6 + 2 * op;
        float bia0 = b2[o], bia1 = b2[o + 1];
        float* e0 = g_enc + ((size_t)b * OE_ + o) * HW_ + (h0 + py) * 64 + w0 + px0;
        float* e1 = e0 + HW_;
#pragma unroll
        for (int p = 0; p < 4; p++) {
            float2 r = up2(acc[op][p]);
            e0[p] = r.x + bia0;
            e1[p] = r.y + bia1;
        }
    }
}

// ---------------- K4: softmax over H, block per (b,ch) ----------------
__global__ __launch_bounds__(256) void k4_softmax()
{
    __shared__ float red[4][64];
    int b = blockIdx.x / 36, ch = blockIdx.x % 36;
    int tid = threadIdx.x;
    int w = tid & 63, hq = tid >> 6;
    float* base = g_enc + ((size_t)b * 36 + ch) * HW_;
    float v[16];
    float m = -1e30f;
#pragma unroll
    for (int i = 0; i < 16; i++) {
        v[i] = base[(hq * 16 + i) * 64 + w];
        m = fmaxf(m, v[i]);
    }
    red[hq][w] = m;
    __syncthreads();
    m = fmaxf(fmaxf(red[0][w], red[1][w]), fmaxf(red[2][w], red[3][w]));
    float s = 0.f;
#pragma unroll
    for (int i = 0; i < 16; i++) { v[i] = __expf(v[i] - m); s += v[i]; }
    __syncthreads();
    red[hq][w] = s;
    __syncthreads();
    float inv = 1.f / (red[0][w] + red[1][w] + red[2][w] + red[3][w]);
#pragma unroll
    for (int i = 0; i < 16; i++) base[(hq * 16 + i) * 64 + w] = v[i] * inv;
}

// ---------------- K5: CARAFE reassembly, f32x2 over w-pairs, STG.64 ----------------
__global__ __launch_bounds__(256) void k5_carafe(
    const float* __restrict__ x, float* __restrict__ out)
{
    __shared__ __align__(16) float xs[3][32][64];
    int h = blockIdx.x, b = blockIdx.y;
    int tid = threadIdx.x;
    int wt2 = tid & 31, cg = tid >> 5;
    int w0 = 2 * wt2;

    u64 kr2[4][9];
    const float* encb = g_enc + (size_t)b * 36 * HW_ + h * 64 + w0;
#pragma unroll
    for (int s = 0; s < 4; s++)
#pragma unroll
        for (int k = 0; k < 9; k++)
            kr2[s][k] = *(const u64*)(encb + (size_t)(s * 9 + k) * HW_);

    int hr0 = h > 0 ? h - 1 : 0;
    int hr2 = h < 63 ? h + 1 : 63;
    int hrow[3] = {hr0, h, hr2};
    int cm1 = w0 > 0 ? w0 - 1 : 0;
    int cp2 = w0 + 2 < 64 ? w0 + 2 : 63;
    float* outb = out + (size_t)b * C_ * 128 * 128;

    for (int cb = 0; cb < 256; cb += 32) {
        __syncthreads();
#pragma unroll
        for (int k = 0; k < 6; k++) {
            int q = tid + k * 256;
            int dr = q / 512;
            int cl = (q >> 4) & 31;
            int wq = q & 15;
            ((float4*)xs)[q] =
                ((const float4*)(x + (((size_t)b * C_ + cb + cl) * 64 + hrow[dr]) * 64))[wq];
        }
        __syncthreads();
#pragma unroll
        for (int cc = 0; cc < 4; cc++) {
            int cl = cg * 4 + cc;
            u64 p[3][3];
#pragma unroll
            for (int r = 0; r < 3; r++) {
                const float* row = &xs[r][cl][0];
                float  a = row[cm1];
                u64    mid = *(const u64*)&row[w0];
                float  d = row[cp2];
                float2 mf = up2(mid);
                p[r][0] = pk2(a, mf.x);
                p[r][1] = mid;
                p[r][2] = pk2(mf.y, d);
            }
            u64 acc[4] = {0ull, 0ull, 0ull, 0ull};
#pragma unroll
            for (int k2 = 0; k2 < 9; k2++) {
                int i = k2 / 3, j = k2 % 3;
                fma2(acc[0], p[i][j], kr2[0][k2]);
                fma2(acc[1], p[i][j], kr2[1][k2]);
                fma2(acc[2], p[i][j], kr2[2][k2]);
                fma2(acc[3], p[i][j], kr2[3][k2]);
            }
            int c = cb + cl;
            int s4 = c & 3;
            int row_o = 2 * h + (s4 >> 1);
            int colb = ((s4 & 1) << 6) + w0;
            int c4b = c >> 2;
#pragma unroll
            for (int s = 0; s < 4; s++)
                *(u64*)&outb[(((size_t)(s * 64 + c4b)) * 128 + row_o) * 128 + colb] = acc[s];
        }
    }
}

// ---------------- launch ----------------
extern "C" void kernel_launch(void* const* d_in, const int* in_sizes, int n_in,
                              void* d_out, int out_size)
{
    const float* x     = (const float*)d_in[0];
    const float* w1    = (const float*)d_in[1];
    const float* b1    = (const float*)d_in[2];
    const float* gamma = (const float*)d_in[3];
    const float* beta  = (const float*)d_in[4];
    const float* w2    = (const float*)d_in[5];
    const float* b2    = (const float*)d_in[6];
    float* out = (float*)d_out;

    k0_wt<<<81, 256>>>(w2);
    k1_compress<<<256, 256>>>(x, w1, b1);
    k2_stats<<<64, 256>>>(gamma, beta);
    k3_conv<<<dim3(4, 8, 8), 192>>>(b2);
    k4_softmax<<<288, 256>>>();
    k5_carafe<<<dim3(64, 8), 256>>>(x, out);
}